// round 6
// baseline (speedup 1.0000x reference)
#include <cuda_runtime.h>
#include <cstdint>

// PatchEmbed permute: x[16,64,256,256] f32 -> out[16, 64*64, 64*4*4]
// out[n, wp, hp, c, pi, pj] = x[n, c, hp*4+pi, wp*4+pj]
// pj (4 floats) => float4 units. Per (n, hp): transpose M[cp=256][wp=64]
// of float4 where cp = c*4+pi.
//   input  f4 idx = ((n*64 + c)*256 + hp*4 + pi)*64 + wp
//   output f4 idx = ((n*64 + wp)*64 + hp)*256 + cp
//
// R6: 3-stage cp.async pipeline over 8 hp-tiles per block, ONE barrier per
// iteration. Order per iter: wait(fill it) -> BAR -> issue fill(it+2) ->
// store(it). The BAR proves store(it-1) drained before fill(it+2) reuses its
// buffer; fills are issued ahead of the store phase so ~2 tile-reads stay in
// flight per block at all times. 3 x 16KB = 48KB smem, 4 blocks x 16 warps =
// 64 warps/SM. XOR swizzle keeps both smem phases conflict-free.

#define N_ 16
#define C_ 64
#define HP_ 64
#define WP_ 64
#define CP_ 256
#define CPT_ 16            // cp per tile
#define HPB_ 8             // hp tiles per block
#define THREADS 512
#define NDATA    (N_ * C_ * 256 * 256)

__global__ __launch_bounds__(THREADS, 4)
void patch_permute_kernel(const float4* __restrict__ in, float4* __restrict__ out,
                          int tail_count) {
    __shared__ float4 tile[3][CPT_][WP_];   // 3 x 16KB = 48KB, XOR-swizzled

    const int cpt = blockIdx.x;    // 0..15  (cp in [cpt*16, cpt*16+16))
    const int hpy = blockIdx.y;    // 0..7   (hp in [hpy*8, hpy*8+8))
    const int n   = blockIdx.z;    // 0..15
    const int tid = threadIdx.x;

    // ---- fused tail write (ori_shape = 16,64,256,256), one block only ----
    if (cpt == 0 && hpy == 0 && n == 0 && tid < 4 && tid < tail_count) {
        const float vals[4] = {16.0f, 64.0f, 256.0f, 256.0f};
        ((float*)out)[NDATA + tid] = vals[tid];
    }

#define FILL(IT, BUF)                                                          \
    {                                                                          \
        int hp = hpy * HPB_ + (IT);                                            \
        _Pragma("unroll")                                                      \
        for (int i = 0; i < (CPT_ * WP_) / THREADS; i++) {   /* 2 iters */     \
            int idx = i * THREADS + tid;                                       \
            int cpl = idx >> 6;          /* 0..15 */                           \
            int wp  = idx & 63;          /* 0..63 */                           \
            int cp  = cpt * CPT_ + cpl;                                        \
            int c   = cp >> 2;                                                 \
            int pi  = cp & 3;                                                  \
            int in_idx = ((n * C_ + c) * 256 + hp * 4 + pi) * WP_ + wp;        \
            uint32_t saddr = (uint32_t)__cvta_generic_to_shared(               \
                &tile[BUF][cpl][wp ^ (cpl & 7)]);                              \
            asm volatile("cp.async.cg.shared.global [%0], [%1], 16;\n"         \
                         :: "r"(saddr), "l"(in + in_idx) : "memory");          \
        }                                                                      \
        asm volatile("cp.async.commit_group;\n" ::: "memory");                 \
    }

#define STORE(IT, BUF)                                                         \
    {                                                                          \
        int hp = hpy * HPB_ + (IT);                                            \
        _Pragma("unroll")                                                      \
        for (int i = 0; i < (CPT_ * WP_) / THREADS; i++) {   /* 2 iters */     \
            int idx = i * THREADS + tid;                                       \
            int wp  = idx >> 4;          /* 0..63 */                           \
            int cpl = idx & 15;          /* 0..15 */                           \
            int cp  = cpt * CPT_ + cpl;                                        \
            int out_idx = ((n * WP_ + wp) * HP_ + hp) * CP_ + cp;              \
            out[out_idx] = tile[BUF][cpl][wp ^ (cpl & 7)];                     \
        }                                                                      \
    }

    FILL(0, 0)
    FILL(1, 1)
#pragma unroll
    for (int it = 0; it < HPB_; it++) {
        // wait for fill(it): allow 1 younger group (fill it+1) to stay pending
        if (it + 1 < HPB_)
            asm volatile("cp.async.wait_group 1;\n" ::: "memory");
        else
            asm volatile("cp.async.wait_group 0;\n" ::: "memory");
        __syncthreads();   // also proves store(it-1) drained (buffer reuse)
        if (it + 2 < HPB_) {
            switch ((it + 2) % 3) {
                case 0: FILL(it + 2, 0) break;
                case 1: FILL(it + 2, 1) break;
                default: FILL(it + 2, 2) break;
            }
        }
        switch (it % 3) {
            case 0: STORE(it, 0) break;
            case 1: STORE(it, 1) break;
            default: STORE(it, 2) break;
        }
    }
}

extern "C" void kernel_launch(void* const* d_in, const int* in_sizes, int n_in,
                              void* d_out, int out_size) {
    (void)in_sizes; (void)n_in;
    const float4* in  = (const float4*)d_in[0];
    float4*       out = (float4*)d_out;

    int tail_count = out_size > NDATA ? (out_size - NDATA) : 0;

    dim3 grid(CP_ / CPT_, HP_ / HPB_, N_);   // 16 x 8 x 16 = 2048 blocks
    patch_permute_kernel<<<grid, THREADS>>>(in, out, tail_count);
}

// round 7
// speedup vs baseline: 1.0300x; 1.0300x over previous
#include <cuda_runtime.h>
#include <cstdint>

// PatchEmbed permute: x[16,64,256,256] f32 -> out[16, 64*64, 64*4*4]
// out[n, wp, hp, c, pi, pj] = x[n, c, hp*4+pi, wp*4+pj]
// pj (4 floats) => float4 units. Per (n, hp): transpose M[cp=256][wp=64]
// of float4 where cp = c*4+pi.
//   input  f4 idx = ((n*64 + c)*256 + hp*4 + pi)*64 + wp   (contiguous in wp)
//   output f4 idx = ((n*64 + wp)*64 + hp)*256 + cp          (contiguous in cp)
//
// R7: kernel is at ~88% of spec HBM (536.9MB / 76.3us = 7.03 TB/s) on a 50/50
// mixed R/W stream -- bandwidth-bound at the achievable ceiling. Final knob:
// 256-thread blocks with 16KB tiles at __launch_bounds__(256,8) -> still
// 64 warps/SM, but barriers span 8 warps (less arrival skew) and 8 independent
// blocks/SM decorrelate fill/store phases. Plain LDG/STG (cp.async + __stcs
// measured neutral). XOR swizzle: col = wp ^ (cpl & 7) keeps both smem phases
// conflict-free (distinct col mod 8 within every 8-lane LDS.128 phase).

#define N_ 16
#define C_ 64
#define HP_ 64
#define WP_ 64
#define CP_ 256            // C_*4
#define CPT_ 16            // cp rows per tile
#define THREADS 256
#define NDATA    (N_ * C_ * 256 * 256)     // data size in floats

__global__ __launch_bounds__(THREADS, 8)
void patch_permute_kernel(const float4* __restrict__ in, float4* __restrict__ out,
                          int tail_count) {
    __shared__ float4 tile[CPT_][WP_];   // 16 KB, XOR-swizzled

    const int cpt = blockIdx.x;    // 0..15  (cp in [cpt*16, cpt*16+16))
    const int hp  = blockIdx.y;    // 0..63
    const int n   = blockIdx.z;    // 0..15
    const int tid = threadIdx.x;

    // ---- fused tail write (ori_shape = 16,64,256,256), one block only ----
    if (cpt == 0 && hp == 0 && n == 0 && tid < 4 && tid < tail_count) {
        const float vals[4] = {16.0f, 64.0f, 256.0f, 256.0f};
        ((float*)out)[NDATA + tid] = vals[tid];
    }

    // ---- load: coalesced over wp (512B per warp), swizzled smem store ----
#pragma unroll
    for (int i = 0; i < (CPT_ * WP_) / THREADS; i++) {   // 4 iters
        int idx = i * THREADS + tid;
        int cpl = idx >> 6;          // 0..15
        int wp  = idx & 63;          // 0..63
        int cp  = cpt * CPT_ + cpl;
        int c   = cp >> 2;
        int pi  = cp & 3;
        int in_idx = ((n * C_ + c) * 256 + hp * 4 + pi) * WP_ + wp;
        tile[cpl][wp ^ (cpl & 7)] = in[in_idx];
    }
    __syncthreads();

    // ---- store: coalesced over cp, swizzled smem read ----
#pragma unroll
    for (int i = 0; i < (CPT_ * WP_) / THREADS; i++) {   // 4 iters
        int idx = i * THREADS + tid;
        int wp  = idx >> 4;          // 0..63
        int cpl = idx & 15;          // 0..15
        int cp  = cpt * CPT_ + cpl;
        int out_idx = ((n * WP_ + wp) * HP_ + hp) * CP_ + cp;
        out[out_idx] = tile[cpl][wp ^ (cpl & 7)];
    }
}

extern "C" void kernel_launch(void* const* d_in, const int* in_sizes, int n_in,
                              void* d_out, int out_size) {
    (void)in_sizes; (void)n_in;
    const float4* in  = (const float4*)d_in[0];
    float4*       out = (float4*)d_out;

    int tail_count = out_size > NDATA ? (out_size - NDATA) : 0;

    dim3 grid(CP_ / CPT_, HP_, N_);   // 16 x 64 x 16 = 16384 blocks
    patch_permute_kernel<<<grid, THREADS>>>(in, out, tail_count);
}